// round 4
// baseline (speedup 1.0000x reference)
#include <cuda_runtime.h>
#include <cuda_bf16.h>
#include <math.h>

// Problem constants
#define BB 64
#define TT 1000
#define NN 512
#define G3 1536          // 3*N
#define GRID_SCAN 128    // cooperative grid size (<= #SMs, must all be co-resident)

// ---------------------------------------------------------------------------
// Scratch (device globals: allocation-free per harness rules)
// ---------------------------------------------------------------------------
__device__ float    g_xproj[BB * TT * G3];   // [B][T][3N]  (~393 MB)
__device__ float    g_h[2][BB * NN];         // double-buffered hidden state
__device__ unsigned g_count;                 // monotonic grid-barrier arrival count
__device__ unsigned g_gen;                   // grid-barrier generation

// ---------------------------------------------------------------------------
// Init: reset barrier state + zero h0 (must run every launch — graph replays)
// ---------------------------------------------------------------------------
__global__ void init_kernel() {
    int i = blockIdx.x * blockDim.x + threadIdx.x;
    if (i == 0) { g_count = 0u; g_gen = 0u; }
    for (int j = i; j < BB * NN; j += gridDim.x * blockDim.x) {
        g_h[0][j] = 0.0f;
    }
}

// ---------------------------------------------------------------------------
// Kernel 1: x_proj[m][g] = sum_k h_enc[m][k] * W_ih[g][k] + b_ih[g]
//   M = 64000 (b*1000+t), Ng = 1536, K = 512.  128x128x16 tiles, 8x8 microtile.
// ---------------------------------------------------------------------------
__global__ void __launch_bounds__(256) xproj_kernel(
    const float* __restrict__ A,     // h_enc [64000][512]
    const float* __restrict__ Wih,   // [1536][512]
    const float* __restrict__ bih,   // [1536]
    float* __restrict__ C)           // g_xproj [64000][1536]
{
    __shared__ float As[16][128];
    __shared__ float Bs[16][128];

    const int tid   = threadIdx.x;            // 256 threads
    const int mBase = blockIdx.y * 128;       // 500 tiles
    const int nBase = blockIdx.x * 128;       // 12 tiles
    const int tx = tid & 15;
    const int ty = tid >> 4;

    float acc[8][8];
#pragma unroll
    for (int i = 0; i < 8; i++)
#pragma unroll
        for (int j = 0; j < 8; j++) acc[i][j] = 0.0f;

    const int lr = tid >> 2;          // 0..63
    const int lk = (tid & 3) << 2;    // 0,4,8,12
    const float* Aptr = A   + (size_t)(mBase + lr) * NN + lk;
    const float* Bptr = Wih + (size_t)(nBase + lr) * NN + lk;

    for (int kt = 0; kt < NN; kt += 16) {
        const float4 a0 = *(const float4*)(Aptr + kt);
        const float4 a1 = *(const float4*)(Aptr + 64 * NN + kt);
        const float4 b0 = *(const float4*)(Bptr + kt);
        const float4 b1 = *(const float4*)(Bptr + 64 * NN + kt);
        __syncthreads();   // previous iteration's reads done before overwrite
        As[lk + 0][lr] = a0.x; As[lk + 1][lr] = a0.y; As[lk + 2][lr] = a0.z; As[lk + 3][lr] = a0.w;
        As[lk + 0][64 + lr] = a1.x; As[lk + 1][64 + lr] = a1.y; As[lk + 2][64 + lr] = a1.z; As[lk + 3][64 + lr] = a1.w;
        Bs[lk + 0][lr] = b0.x; Bs[lk + 1][lr] = b0.y; Bs[lk + 2][lr] = b0.z; Bs[lk + 3][lr] = b0.w;
        Bs[lk + 0][64 + lr] = b1.x; Bs[lk + 1][64 + lr] = b1.y; Bs[lk + 2][64 + lr] = b1.z; Bs[lk + 3][64 + lr] = b1.w;
        __syncthreads();
#pragma unroll
        for (int k = 0; k < 16; k++) {
            float af[8], bf[8];
            *(float4*)&af[0] = *(const float4*)&As[k][ty * 4];
            *(float4*)&af[4] = *(const float4*)&As[k][64 + ty * 4];
            *(float4*)&bf[0] = *(const float4*)&Bs[k][tx * 4];
            *(float4*)&bf[4] = *(const float4*)&Bs[k][64 + tx * 4];
#pragma unroll
            for (int i = 0; i < 8; i++)
#pragma unroll
                for (int j = 0; j < 8; j++)
                    acc[i][j] = fmaf(af[i], bf[j], acc[i][j]);
        }
    }

    // epilogue: add bias, write float4 pairs
    float bias[8];
#pragma unroll
    for (int j = 0; j < 8; j++) {
        int col = nBase + ((j < 4) ? (tx * 4 + j) : (64 + tx * 4 + (j - 4)));
        bias[j] = __ldg(&bih[col]);
    }
#pragma unroll
    for (int i = 0; i < 8; i++) {
        int row = mBase + ((i < 4) ? (ty * 4 + i) : (64 + ty * 4 + (i - 4)));
        float* cp = C + (size_t)row * G3 + nBase;
        float4 lo = make_float4(acc[i][0] + bias[0], acc[i][1] + bias[1],
                                acc[i][2] + bias[2], acc[i][3] + bias[3]);
        float4 hi = make_float4(acc[i][4] + bias[4], acc[i][5] + bias[5],
                                acc[i][6] + bias[6], acc[i][7] + bias[7]);
        *(float4*)(cp + tx * 4)      = lo;
        *(float4*)(cp + 64 + tx * 4) = hi;
    }
}

// ---------------------------------------------------------------------------
// Kernel 2: persistent cooperative GRU scan.
//   128 CTAs x 256 threads. CTA owns hidden cols [n0, n0+4). Its 12 W_hh rows
//   (r,z,n gates) live in SMEM the whole kernel. Thread (b,nn) computes all 3
//   gates for output (b, n0+nn). h double-buffered in global (L2-resident),
//   grid barrier per step via monotonic arrival counter.
// ---------------------------------------------------------------------------
__global__ void __launch_bounds__(256) gru_scan_kernel(
    const float* __restrict__ Whh,   // [1536][512]
    const float* __restrict__ bhh,   // [1536]
    float* __restrict__ out)         // [B][T][N]
{
    __shared__ float ws[12][NN];     // W_hh slice: [gate*4 + nn][k]   (24 KB)
    __shared__ float xs[3][4][64];   // x_t slice:  [gate][nn][b]      (3 KB)
    __shared__ float hs[4][64];      // h_new:      [nn][b]            (1 KB)

    const int tid = threadIdx.x;
    const int n0  = blockIdx.x * 4;
    const int b   = tid & 63;
    const int nn  = tid >> 6;

    // Load W_hh slice once (coalesced float4 along k)
    for (int i = tid; i < 12 * 128; i += 256) {
        const int row = i >> 7;          // 0..11 = gate*4 + jn
        const int c4  = i & 127;
        const int gate = row >> 2;
        const int jn   = row & 3;
        const float4 v = __ldg((const float4*)(Whh + (size_t)(gate * NN + n0 + jn) * NN) + c4);
        *(float4*)&ws[row][c4 * 4] = v;
    }

    const float bhr = __ldg(&bhh[n0 + nn]);
    const float bhz = __ldg(&bhh[NN + n0 + nn]);
    const float bhn = __ldg(&bhh[2 * NN + n0 + nn]);

    const float4* w0 = (const float4*)ws[nn];       // r
    const float4* w1 = (const float4*)ws[4 + nn];   // z
    const float4* w2 = (const float4*)ws[8 + nn];   // n
    __syncthreads();

    for (int t = 0; t < TT; t++) {
        const float* hcur = g_h[t & 1];
        float*       hnxt = g_h[(t & 1) ^ 1];

        // Stage x_proj[:, t, slice] into SMEM (float4 per (b, gate))
        if (tid < 192) {
            const int grp = tid >> 6;   // gate 0..2
            const int bb  = tid & 63;
            const float4 xv = __ldg((const float4*)(
                g_xproj + (size_t)(bb * TT + t) * G3 + grp * NN + n0));
            xs[grp][0][bb] = xv.x; xs[grp][1][bb] = xv.y;
            xs[grp][2][bb] = xv.z; xs[grp][3][bb] = xv.w;
        }
        __syncthreads();

        // gates_h = h . W_hh^T for this thread's (b, n0+nn)
        float ar = 0.0f, az = 0.0f, an = 0.0f;
        const float4* hb4 = (const float4*)(hcur + b * NN);
#pragma unroll 8
        for (int k = 0; k < NN / 4; k++) {
            const float4 h4 = __ldg(&hb4[k]);
            const float4 wa = w0[k];
            const float4 wb = w1[k];
            const float4 wc = w2[k];
            ar = fmaf(h4.x, wa.x, ar); ar = fmaf(h4.y, wa.y, ar);
            ar = fmaf(h4.z, wa.z, ar); ar = fmaf(h4.w, wa.w, ar);
            az = fmaf(h4.x, wb.x, az); az = fmaf(h4.y, wb.y, az);
            az = fmaf(h4.z, wb.z, az); az = fmaf(h4.w, wb.w, az);
            an = fmaf(h4.x, wc.x, an); an = fmaf(h4.y, wc.y, an);
            an = fmaf(h4.z, wc.z, an); an = fmaf(h4.w, wc.w, an);
        }

        const float hprev = hcur[b * NN + n0 + nn];
        const float xr = xs[0][nn][b];
        const float xz = xs[1][nn][b];
        const float xn = xs[2][nn][b];

        const float r  = 1.0f / (1.0f + __expf(-(xr + ar + bhr)));
        const float z  = 1.0f / (1.0f + __expf(-(xz + az + bhz)));
        const float nv = tanhf(xn + r * (an + bhn));
        const float hnew = (1.0f - z) * nv + z * hprev;

        hs[nn][b] = hnew;
        __syncthreads();

        // Packed float4 writeback of h_new slice (global state + output)
        if (tid < 64) {
            const float4 v = make_float4(hs[0][tid], hs[1][tid], hs[2][tid], hs[3][tid]);
            *(float4*)(hnxt + tid * NN + n0) = v;
            *(float4*)(out + (size_t)(tid * TT + t) * NN + n0) = v;
            __threadfence();   // push h_new to L2 before barrier arrival
        }
        __syncthreads();

        // Grid barrier (skip after last step). Monotonic count: all arrivals
        // for step t happen before any arrival for step t+1 is possible.
        if (t < TT - 1) {
            if (tid == 0) {
                const unsigned target = (unsigned)(t + 1);
                const unsigned arrived = atomicAdd(&g_count, 1u) + 1u;
                if (arrived == target * (unsigned)GRID_SCAN) {
                    atomicExch(&g_gen, target);
                } else {
                    volatile unsigned* vg = &g_gen;
                    while (*vg < target) { }
                }
            }
            __syncthreads();
            __threadfence();   // acquire: see other CTAs' h_new writes
        }
    }
}

// ---------------------------------------------------------------------------
// Launch
// ---------------------------------------------------------------------------
extern "C" void kernel_launch(void* const* d_in, const int* in_sizes, int n_in,
                              void* d_out, int out_size) {
    const float* h_enc = (const float*)d_in[0];   // [64,1000,512]
    const float* W_ih  = (const float*)d_in[1];   // [1536,512]
    const float* W_hh  = (const float*)d_in[2];   // [1536,512]
    const float* b_ih  = (const float*)d_in[3];   // [1536]
    const float* b_hh  = (const float*)d_in[4];   // [1536]
    float* out = (float*)d_out;                    // [64,1000,512]

    float* xproj_ptr = nullptr;
    cudaGetSymbolAddress((void**)&xproj_ptr, g_xproj);

    // 1) reset barrier + zero h0 (needed on every graph replay)
    init_kernel<<<128, 256>>>();

    // 2) x_proj = h_enc @ W_ih^T + b_ih   (grid 12 x 500)
    {
        dim3 grid(G3 / 128, (BB * TT) / 128);
        xproj_kernel<<<grid, 256>>>(h_enc, W_ih, b_ih, xproj_ptr);
    }

    // 3) persistent cooperative scan
    gru_scan_kernel<<<GRID_SCAN, 256>>>(W_hh, b_hh, out);
}